// round 3
// baseline (speedup 1.0000x reference)
#include <cuda_runtime.h>
#include <math.h>

// Problem constants
#define BATCH 8
#define SEQ   1024
#define CH    768
#define NH    12
#define HD    64
#define BHNUM (BATCH*NH)          // 96
#define MROWS (BATCH*SEQ)         // 8192

// Scratch (static __device__ arrays — no runtime allocation allowed)
__device__ float g_q[BHNUM*SEQ*HD];     // [B,H,N,D]
__device__ float g_k[BHNUM*SEQ*HD];
__device__ float g_v[BHNUM*SEQ*HD];
__device__ float g_ctx[MROWS*CH];       // [B,N,C] = [B,N,H*D]

// ---------------------------------------------------------------------------
// Kernel 1: QKV GEMM.  C1 = x[8192,768] @ w_qkv[768,2304], scatter to Q/K/V.
// 128x128x8 tile, 8x8 per thread, 256 threads.
// ---------------------------------------------------------------------------
__global__ __launch_bounds__(256) void k_qkv(const float* __restrict__ A,
                                             const float* __restrict__ B)
{
    const int K = CH;            // 768
    const int N = 3*CH;          // 2304
    const int m0 = blockIdx.y * 128;
    const int n0 = blockIdx.x * 128;

    __shared__ float As[8][132];     // transposed A tile, padded
    __shared__ float Bs[8][128];

    const int tid = threadIdx.x;
    const int tr = tid >> 4;         // 0..15
    const int tc = tid & 15;         // 0..15

    const int rowA  = tid >> 1;      // 0..127
    const int colA4 = tid & 1;       // 0..1  (2 float4 per 8-wide row)
    const int rowB  = tid >> 5;      // 0..7
    const int colB4 = tid & 31;      // 0..31

    float acc[8][8];
    #pragma unroll
    for (int i = 0; i < 8; i++)
        #pragma unroll
        for (int j = 0; j < 8; j++) acc[i][j] = 0.f;

    for (int k0 = 0; k0 < K; k0 += 8) {
        float4 a = *(const float4*)&A[(size_t)(m0 + rowA) * K + k0 + colA4 * 4];
        As[colA4*4+0][rowA] = a.x;
        As[colA4*4+1][rowA] = a.y;
        As[colA4*4+2][rowA] = a.z;
        As[colA4*4+3][rowA] = a.w;
        *(float4*)&Bs[rowB][colB4*4] =
            *(const float4*)&B[(size_t)(k0 + rowB) * N + n0 + colB4 * 4];
        __syncthreads();

        #pragma unroll
        for (int kk = 0; kk < 8; kk++) {
            float rm[8], rn[8];
            *(float4*)&rm[0] = *(const float4*)&As[kk][tr*8];
            *(float4*)&rm[4] = *(const float4*)&As[kk][tr*8+4];
            *(float4*)&rn[0] = *(const float4*)&Bs[kk][tc*8];
            *(float4*)&rn[4] = *(const float4*)&Bs[kk][tc*8+4];
            #pragma unroll
            for (int i = 0; i < 8; i++)
                #pragma unroll
                for (int j = 0; j < 8; j++)
                    acc[i][j] += rm[i] * rn[j];
        }
        __syncthreads();
    }

    // Scatter epilogue: col -> (which, head, d); row -> (b, n)
    #pragma unroll
    for (int i = 0; i < 8; i++) {
        int row = m0 + tr*8 + i;
        int b = row >> 10;
        int n = row & 1023;
        #pragma unroll
        for (int j = 0; j < 8; j++) {
            int col = n0 + tc*8 + j;
            int which = col / CH;
            int cc = col - which * CH;
            int h = cc >> 6;
            int d = cc & 63;
            float* dst = (which == 0) ? g_q : ((which == 1) ? g_k : g_v);
            dst[(size_t)((b*NH + h)*SEQ + n) * HD + d] = acc[i][j];
        }
    }
}

// ---------------------------------------------------------------------------
// Kernel 2: scores.  Per (b,h): S = Q[1024,64] @ K^T * 0.125 -> attn (raw).
// 64x64x16 tile, 4x4 per thread, 256 threads.  B operand loaded transposed.
// ---------------------------------------------------------------------------
__global__ __launch_bounds__(256) void k_scores(float* __restrict__ attn)
{
    const int bh = blockIdx.z;
    const float* Qp = g_q + (size_t)bh * SEQ * HD;
    const float* Kp = g_k + (size_t)bh * SEQ * HD;
    float* C = attn + (size_t)bh * SEQ * SEQ;

    const int m0 = blockIdx.y * 64;
    const int n0 = blockIdx.x * 64;

    __shared__ float As[16][68];
    __shared__ float Bs[16][68];

    const int tid = threadIdx.x;
    const int tr = tid >> 4;         // 0..15
    const int tc = tid & 15;         // 0..15

    const int rowA  = tid >> 2;      // 0..63
    const int colA4 = tid & 3;       // 0..3

    float acc[4][4];
    #pragma unroll
    for (int i = 0; i < 4; i++)
        #pragma unroll
        for (int j = 0; j < 4; j++) acc[i][j] = 0.f;

    for (int k0 = 0; k0 < HD; k0 += 16) {
        // A tile: Q[m0..m0+63][k0..k0+15], transposed into As
        float4 a = *(const float4*)&Qp[(size_t)(m0 + rowA) * HD + k0 + colA4*4];
        As[colA4*4+0][rowA] = a.x;
        As[colA4*4+1][rowA] = a.y;
        As[colA4*4+2][rowA] = a.z;
        As[colA4*4+3][rowA] = a.w;
        // B^T tile: Bs[k][n] = K[(n0+n)][k0+k]
        float4 bt = *(const float4*)&Kp[(size_t)(n0 + rowA) * HD + k0 + colA4*4];
        Bs[colA4*4+0][rowA] = bt.x;
        Bs[colA4*4+1][rowA] = bt.y;
        Bs[colA4*4+2][rowA] = bt.z;
        Bs[colA4*4+3][rowA] = bt.w;
        __syncthreads();

        #pragma unroll
        for (int kk = 0; kk < 16; kk++) {
            float4 m4 = *(const float4*)&As[kk][tr*4];
            float4 n4 = *(const float4*)&Bs[kk][tc*4];
            float rm[4] = {m4.x, m4.y, m4.z, m4.w};
            float rn[4] = {n4.x, n4.y, n4.z, n4.w};
            #pragma unroll
            for (int i = 0; i < 4; i++)
                #pragma unroll
                for (int j = 0; j < 4; j++)
                    acc[i][j] += rm[i] * rn[j];
        }
        __syncthreads();
    }

    const float scale = 0.125f;   // 1/sqrt(64)
    #pragma unroll
    for (int i = 0; i < 4; i++) {
        int row = m0 + tr*4 + i;
        float4 o = make_float4(acc[i][0]*scale, acc[i][1]*scale,
                               acc[i][2]*scale, acc[i][3]*scale);
        *(float4*)&C[(size_t)row * SEQ + n0 + tc*4] = o;
    }
}

// ---------------------------------------------------------------------------
// Kernel 3: softmax in place on attn rows (length 1024). One block per row.
// Values kept in registers: 1 gmem read, 1 gmem write per element.
// ---------------------------------------------------------------------------
__global__ __launch_bounds__(256) void k_softmax(float* __restrict__ attn)
{
    float* p = attn + (size_t)blockIdx.x * SEQ;
    const int tid = threadIdx.x;

    float4 v = *(const float4*)&p[tid * 4];

    __shared__ float red[8];

    float mx = fmaxf(fmaxf(v.x, v.y), fmaxf(v.z, v.w));
    #pragma unroll
    for (int o = 16; o > 0; o >>= 1)
        mx = fmaxf(mx, __shfl_xor_sync(0xffffffffu, mx, o));
    if ((tid & 31) == 0) red[tid >> 5] = mx;
    __syncthreads();
    float m = red[0];
    #pragma unroll
    for (int i = 1; i < 8; i++) m = fmaxf(m, red[i]);
    __syncthreads();

    v.x = __expf(v.x - m);
    v.y = __expf(v.y - m);
    v.z = __expf(v.z - m);
    v.w = __expf(v.w - m);

    float s = v.x + v.y + v.z + v.w;
    #pragma unroll
    for (int o = 16; o > 0; o >>= 1)
        s += __shfl_xor_sync(0xffffffffu, s, o);
    if ((tid & 31) == 0) red[tid >> 5] = s;
    __syncthreads();
    float tot = red[0];
    #pragma unroll
    for (int i = 1; i < 8; i++) tot += red[i];

    float inv = 1.0f / tot;
    v.x *= inv; v.y *= inv; v.z *= inv; v.w *= inv;
    *(float4*)&p[tid * 4] = v;
}

// ---------------------------------------------------------------------------
// Kernel 4: ctx.  Per (b,h): ctx = P[1024,1024] @ V[1024,64], scatter to
// g_ctx[B,N,C].  64x64x16 tile, 4x4 per thread.
// ---------------------------------------------------------------------------
__global__ __launch_bounds__(256) void k_ctx(const float* __restrict__ attn)
{
    const int bh = blockIdx.z;
    const int b = bh / NH;
    const int h = bh - b * NH;
    const float* A = attn + (size_t)bh * SEQ * SEQ;
    const float* V = g_v + (size_t)bh * SEQ * HD;

    const int m0 = blockIdx.y * 64;     // n0 == 0 (N = 64 exactly)

    __shared__ float As[16][68];
    __shared__ float Bs[16][64];

    const int tid = threadIdx.x;
    const int tr = tid >> 4;
    const int tc = tid & 15;

    const int rowA  = tid >> 2;      // 0..63
    const int colA4 = tid & 3;       // 0..3
    const int rowB  = tid >> 4;      // 0..15
    const int colB4 = tid & 15;      // 0..15

    float acc[4][4];
    #pragma unroll
    for (int i = 0; i < 4; i++)
        #pragma unroll
        for (int j = 0; j < 4; j++) acc[i][j] = 0.f;

    for (int k0 = 0; k0 < SEQ; k0 += 16) {
        float4 a = *(const float4*)&A[(size_t)(m0 + rowA) * SEQ + k0 + colA4*4];
        As[colA4*4+0][rowA] = a.x;
        As[colA4*4+1][rowA] = a.y;
        As[colA4*4+2][rowA] = a.z;
        As[colA4*4+3][rowA] = a.w;
        *(float4*)&Bs[rowB][colB4*4] =
            *(const float4*)&V[(size_t)(k0 + rowB) * HD + colB4*4];
        __syncthreads();

        #pragma unroll
        for (int kk = 0; kk < 16; kk++) {
            float4 m4 = *(const float4*)&As[kk][tr*4];
            float4 n4 = *(const float4*)&Bs[kk][tc*4];
            float rm[4] = {m4.x, m4.y, m4.z, m4.w};
            float rn[4] = {n4.x, n4.y, n4.z, n4.w};
            #pragma unroll
            for (int i = 0; i < 4; i++)
                #pragma unroll
                for (int j = 0; j < 4; j++)
                    acc[i][j] += rm[i] * rn[j];
        }
        __syncthreads();
    }

    // Scatter: g_ctx[(b*SEQ + n) * CH + h*HD + d]
    #pragma unroll
    for (int i = 0; i < 4; i++) {
        int n = m0 + tr*4 + i;
        float4 o = make_float4(acc[i][0], acc[i][1], acc[i][2], acc[i][3]);
        *(float4*)&g_ctx[(size_t)(b*SEQ + n) * CH + h*HD + tc*4] = o;
    }
}

// ---------------------------------------------------------------------------
// Kernel 5: out = ctx[8192,768] @ w_proj[768,768] + b_proj.
// 128x128x8 tile, 8x8 per thread, 256 threads.
// ---------------------------------------------------------------------------
__global__ __launch_bounds__(256) void k_proj(const float* __restrict__ B,
                                              const float* __restrict__ bias,
                                              float* __restrict__ out)
{
    const int K = CH, N = CH;
    const int m0 = blockIdx.y * 128;
    const int n0 = blockIdx.x * 128;

    __shared__ float As[8][132];
    __shared__ float Bs[8][128];

    const int tid = threadIdx.x;
    const int tr = tid >> 4;
    const int tc = tid & 15;

    const int rowA  = tid >> 1;
    const int colA4 = tid & 1;
    const int rowB  = tid >> 5;
    const int colB4 = tid & 31;

    float acc[8][8];
    #pragma unroll
    for (int i = 0; i < 8; i++)
        #pragma unroll
        for (int j = 0; j < 8; j++) acc[i][j] = 0.f;

    for (int k0 = 0; k0 < K; k0 += 8) {
        float4 a = *(const float4*)&g_ctx[(size_t)(m0 + rowA) * K + k0 + colA4*4];
        As[colA4*4+0][rowA] = a.x;
        As[colA4*4+1][rowA] = a.y;
        As[colA4*4+2][rowA] = a.z;
        As[colA4*4+3][rowA] = a.w;
        *(float4*)&Bs[rowB][colB4*4] =
            *(const float4*)&B[(size_t)(k0 + rowB) * N + n0 + colB4*4];
        __syncthreads();

        #pragma unroll
        for (int kk = 0; kk < 8; kk++) {
            float rm[8], rn[8];
            *(float4*)&rm[0] = *(const float4*)&As[kk][tr*8];
            *(float4*)&rm[4] = *(const float4*)&As[kk][tr*8+4];
            *(float4*)&rn[0] = *(const float4*)&Bs[kk][tc*8];
            *(float4*)&rn[4] = *(const float4*)&Bs[kk][tc*8+4];
            #pragma unroll
            for (int i = 0; i < 8; i++)
                #pragma unroll
                for (int j = 0; j < 8; j++)
                    acc[i][j] += rm[i] * rn[j];
        }
        __syncthreads();
    }

    #pragma unroll
    for (int i = 0; i < 8; i++) {
        int row = m0 + tr*8 + i;
        #pragma unroll
        for (int j = 0; j < 8; j += 4) {
            int col = n0 + tc*8 + j;
            float4 bv = *(const float4*)&bias[col];
            float4 o = make_float4(acc[i][j+0] + bv.x, acc[i][j+1] + bv.y,
                                   acc[i][j+2] + bv.z, acc[i][j+3] + bv.w);
            *(float4*)&out[(size_t)row * N + col] = o;
        }
    }
}

// ---------------------------------------------------------------------------
extern "C" void kernel_launch(void* const* d_in, const int* in_sizes, int n_in,
                              void* d_out, int out_size)
{
    const float* x      = (const float*)d_in[0];
    const float* w_qkv  = (const float*)d_in[1];
    const float* w_proj = (const float*)d_in[2];
    const float* b_proj = (const float*)d_in[3];

    float* out  = (float*)d_out;
    float* attn = out + (size_t)MROWS * CH;   // out first, then attn

    // 1. QKV projection
    k_qkv<<<dim3(3*CH/128, MROWS/128), 256>>>(x, w_qkv);

    // 2. Raw scores -> attn region
    k_scores<<<dim3(SEQ/64, SEQ/64, BHNUM), 256>>>(attn);

    // 3. Softmax in place
    k_softmax<<<dim3(BHNUM * SEQ), 256>>>(attn);

    // 4. ctx = P @ V
    k_ctx<<<dim3(1, SEQ/64, BHNUM), 256>>>(attn);

    // 5. Output projection + bias
    k_proj<<<dim3(CH/128, MROWS/128), 256>>>(w_proj, b_proj, out);
}

// round 5
// speedup vs baseline: 2.6648x; 2.6648x over previous
#include <cuda_runtime.h>
#include <cuda_bf16.h>
#include <math.h>

#define BATCH 8
#define SEQ   1024
#define CH    768
#define NH    12
#define HD    64
#define BHNUM (BATCH*NH)          // 96
#define MROWS (BATCH*SEQ)         // 8192
#define KP    40                  // smem row pitch (bf16 elems) for K-chunk 32

typedef __nv_bfloat16  bf16;
typedef __nv_bfloat162 bf162;

// ---- persistent scratch (__device__ globals; no runtime allocation) ----
__device__ bf16 g_q_h[BHNUM*SEQ*HD],  g_q_l[BHNUM*SEQ*HD];    // [bh][seq][d]
__device__ bf16 g_k_h[BHNUM*SEQ*HD],  g_k_l[BHNUM*SEQ*HD];    // [bh][seq][d]
__device__ bf16 g_vt_h[BHNUM*HD*SEQ], g_vt_l[BHNUM*HD*SEQ];   // [bh][d][seq]
__device__ bf16 g_ctx_h[MROWS*CH],    g_ctx_l[MROWS*CH];      // [m][c]
__device__ bf16 g_wq_h[3*CH*CH],      g_wq_l[3*CH*CH];        // [n=2304][k=768]
__device__ bf16 g_wp_h[CH*CH],        g_wp_l[CH*CH];          // [n=768][k=768]

// ---- helpers ----
__device__ __forceinline__ void bsplit(float v, bf16& h, bf16& l) {
    h = __float2bfloat16(v);
    l = __float2bfloat16(v - __bfloat162float(h));
}
__device__ __forceinline__ void bsplit2(float x, float y, bf162& h, bf162& l) {
    h.x = __float2bfloat16(x); l.x = __float2bfloat16(x - __bfloat162float(h.x));
    h.y = __float2bfloat16(y); l.y = __float2bfloat16(y - __bfloat162float(h.y));
}

__device__ __forceinline__ void mma_bf16(float* c, unsigned a0, unsigned a1,
                                         unsigned a2, unsigned a3,
                                         unsigned b0, unsigned b1) {
    asm volatile(
        "mma.sync.aligned.m16n8k16.row.col.f32.bf16.bf16.f32 "
        "{%0,%1,%2,%3}, {%4,%5,%6,%7}, {%8,%9}, {%0,%1,%2,%3};\n"
        : "+f"(c[0]), "+f"(c[1]), "+f"(c[2]), "+f"(c[3])
        : "r"(a0), "r"(a1), "r"(a2), "r"(a3), "r"(b0), "r"(b1));
}

// One k16 step of split-bf16 mma over an MT x NT warp tile.
// A tiles: row-major [row][KP] (k contiguous). B tiles: [n][KP] (k contiguous).
template<int MT, int NT>
__device__ __forceinline__ void mma_step(const bf16* __restrict__ Ah,
                                         const bf16* __restrict__ Al,
                                         const bf16* __restrict__ Bh,
                                         const bf16* __restrict__ Bl,
                                         int mbase, int nbase, int kk,
                                         int g, int t4,
                                         float (&c)[MT][NT][4]) {
    unsigned bh[NT][2], bl[NT][2];
    #pragma unroll
    for (int nt = 0; nt < NT; nt++) {
        int nr = (nbase + nt*8 + g) * KP + kk + 2*t4;
        bh[nt][0] = *(const unsigned*)&Bh[nr];
        bh[nt][1] = *(const unsigned*)&Bh[nr + 8];
        bl[nt][0] = *(const unsigned*)&Bl[nr];
        bl[nt][1] = *(const unsigned*)&Bl[nr + 8];
    }
    #pragma unroll
    for (int mt = 0; mt < MT; mt++) {
        int r0 = (mbase + mt*16 + g) * KP + kk + 2*t4;
        int r1 = r0 + 8*KP;
        unsigned a0h = *(const unsigned*)&Ah[r0];
        unsigned a1h = *(const unsigned*)&Ah[r1];
        unsigned a2h = *(const unsigned*)&Ah[r0 + 8];
        unsigned a3h = *(const unsigned*)&Ah[r1 + 8];
        unsigned a0l = *(const unsigned*)&Al[r0];
        unsigned a1l = *(const unsigned*)&Al[r1];
        unsigned a2l = *(const unsigned*)&Al[r0 + 8];
        unsigned a3l = *(const unsigned*)&Al[r1 + 8];
        #pragma unroll
        for (int nt = 0; nt < NT; nt++) {
            mma_bf16(c[mt][nt], a0h, a1h, a2h, a3h, bh[nt][0], bh[nt][1]);
            mma_bf16(c[mt][nt], a0h, a1h, a2h, a3h, bl[nt][0], bl[nt][1]);
            mma_bf16(c[mt][nt], a0l, a1l, a2l, a3l, bh[nt][0], bh[nt][1]);
        }
    }
}

// ---------------------------------------------------------------------------
// Prep: transpose + split fp32 weight [K][N] -> bf16 hi/lo [N][K]
// ---------------------------------------------------------------------------
__global__ void k_tw(const float* __restrict__ W, bf16* __restrict__ Th,
                     bf16* __restrict__ Tl, int K, int N)
{
    __shared__ float t[32][33];
    int k0 = blockIdx.y * 32, n0 = blockIdx.x * 32;
    int tx = threadIdx.x, ty = threadIdx.y;
    #pragma unroll
    for (int i = 0; i < 32; i += 8)
        t[ty + i][tx] = W[(size_t)(k0 + ty + i) * N + n0 + tx];
    __syncthreads();
    #pragma unroll
    for (int i = 0; i < 32; i += 8) {
        float v = t[tx][ty + i];
        bf16 h, l; bsplit(v, h, l);
        size_t o = (size_t)(n0 + ty + i) * K + k0 + tx;
        Th[o] = h; Tl[o] = l;
    }
}

// ---------------------------------------------------------------------------
// K1: QKV GEMM.  x[8192,768] @ w_qkv -> split bf16 Q/K/V (V transposed).
// Block 128x128, 8 warps (2x4), warp tile 64x32, KC=32.
// ---------------------------------------------------------------------------
__global__ __launch_bounds__(256) void k_qkv(const float* __restrict__ X)
{
    const int K = CH;
    const int m0 = blockIdx.y * 128, n0 = blockIdx.x * 128;

    __shared__ bf16 Ah[128*KP], Al[128*KP], Bh[128*KP], Bl[128*KP];

    const int tid = threadIdx.x, lane = tid & 31, w = tid >> 5;
    const int g = lane >> 2, t4 = lane & 3;
    const int wm = w & 1, wn = w >> 1;

    const int lr = tid >> 1, lh = (tid & 1) * 16;

    float c[4][4][4];
    #pragma unroll
    for (int a = 0; a < 4; a++)
        #pragma unroll
        for (int b = 0; b < 4; b++)
            #pragma unroll
            for (int i = 0; i < 4; i++) c[a][b][i] = 0.f;

    for (int k0 = 0; k0 < K; k0 += 32) {
        // A: x rows, split fp32 -> hi/lo
        #pragma unroll
        for (int i = 0; i < 4; i++) {
            float4 v = *(const float4*)&X[(size_t)(m0 + lr) * K + k0 + lh + 4*i];
            bf162 h2a, l2a, h2b, l2b;
            bsplit2(v.x, v.y, h2a, l2a);
            bsplit2(v.z, v.w, h2b, l2b);
            *(bf162*)&Ah[lr*KP + lh + 4*i    ] = h2a;
            *(bf162*)&Ah[lr*KP + lh + 4*i + 2] = h2b;
            *(bf162*)&Al[lr*KP + lh + 4*i    ] = l2a;
            *(bf162*)&Al[lr*KP + lh + 4*i + 2] = l2b;
        }
        // B: pre-transposed weight [n][k], straight bf16 copy
        #pragma unroll
        for (int i = 0; i < 2; i++) {
            *(uint4*)&Bh[lr*KP + lh + 8*i] =
                *(const uint4*)&g_wq_h[(size_t)(n0 + lr) * K + k0 + lh + 8*i];
            *(uint4*)&Bl[lr*KP + lh + 8*i] =
                *(const uint4*)&g_wq_l[(size_t)(n0 + lr) * K + k0 + lh + 8*i];
        }
        __syncthreads();
        mma_step<4,4>(Ah, Al, Bh, Bl, wm*64, wn*32, 0,  g, t4, c);
        mma_step<4,4>(Ah, Al, Bh, Bl, wm*64, wn*32, 16, g, t4, c);
        __syncthreads();
    }

    // Epilogue: split + scatter to Q/K/V (V transposed)
    const int which = n0 / CH;          // block never straddles (768 = 6*128)
    const int cb = n0 - which * CH;
    bf16 *dh, *dl;
    if (which == 0)      { dh = g_q_h;  dl = g_q_l;  }
    else if (which == 1) { dh = g_k_h;  dl = g_k_l;  }
    else                 { dh = g_vt_h; dl = g_vt_l; }
    const bool isv = (which == 2);

    #pragma unroll
    for (int mt = 0; mt < 4; mt++)
        #pragma unroll
        for (int nt = 0; nt < 4; nt++) {
            int nloc = cb + wn*32 + nt*8 + 2*t4;
            int h = nloc >> 6, d0 = nloc & 63;
            #pragma unroll
            for (int i = 0; i < 4; i++) {
                int m = m0 + wm*64 + mt*16 + g + 8*(i >> 1);
                int d = d0 + (i & 1);
                int b = m >> 10, sq = m & 1023;
                bf16 hh, ll; bsplit(c[mt][nt][i], hh, ll);
                size_t idx = isv
                    ? ((size_t)((b*NH + h)*HD + d))*SEQ + sq
                    : ((size_t)((b*NH + h)*SEQ + sq))*HD + d;
                dh[idx] = hh; dl[idx] = ll;
            }
        }
}

// ---------------------------------------------------------------------------
// K2: scores.  S = Q @ K^T * 0.125 -> attn (raw, fp32).
// Block 128x128 per (bh), warp tile 64x32, K=64 in two KC=32 chunks.
// ---------------------------------------------------------------------------
__global__ __launch_bounds__(256) void k_scores(float* __restrict__ attn)
{
    const int bh = blockIdx.z;
    const int m0 = blockIdx.y * 128, n0 = blockIdx.x * 128;

    __shared__ bf16 Ah[128*KP], Al[128*KP], Bh[128*KP], Bl[128*KP];

    const int tid = threadIdx.x, lane = tid & 31, w = tid >> 5;
    const int g = lane >> 2, t4 = lane & 3;
    const int wm = w & 1, wn = w >> 1;
    const int lr = tid >> 1, lh = (tid & 1) * 16;

    const bf16* qh = g_q_h + ((size_t)bh*SEQ + m0) * HD;
    const bf16* ql = g_q_l + ((size_t)bh*SEQ + m0) * HD;
    const bf16* kh = g_k_h + ((size_t)bh*SEQ + n0) * HD;
    const bf16* kl = g_k_l + ((size_t)bh*SEQ + n0) * HD;

    float c[4][4][4];
    #pragma unroll
    for (int a = 0; a < 4; a++)
        #pragma unroll
        for (int b = 0; b < 4; b++)
            #pragma unroll
            for (int i = 0; i < 4; i++) c[a][b][i] = 0.f;

    #pragma unroll
    for (int k0 = 0; k0 < HD; k0 += 32) {
        #pragma unroll
        for (int i = 0; i < 2; i++) {
            *(uint4*)&Ah[lr*KP + lh + 8*i] = *(const uint4*)&qh[lr*HD + k0 + lh + 8*i];
            *(uint4*)&Al[lr*KP + lh + 8*i] = *(const uint4*)&ql[lr*HD + k0 + lh + 8*i];
            *(uint4*)&Bh[lr*KP + lh + 8*i] = *(const uint4*)&kh[lr*HD + k0 + lh + 8*i];
            *(uint4*)&Bl[lr*KP + lh + 8*i] = *(const uint4*)&kl[lr*HD + k0 + lh + 8*i];
        }
        __syncthreads();
        mma_step<4,4>(Ah, Al, Bh, Bl, wm*64, wn*32, 0,  g, t4, c);
        mma_step<4,4>(Ah, Al, Bh, Bl, wm*64, wn*32, 16, g, t4, c);
        __syncthreads();
    }

    const float s = 0.125f;
    float* C = attn + (size_t)bh * SEQ * SEQ;
    #pragma unroll
    for (int mt = 0; mt < 4; mt++)
        #pragma unroll
        for (int nt = 0; nt < 4; nt++) {
            int n = n0 + wn*32 + nt*8 + 2*t4;
            int m = m0 + wm*64 + mt*16 + g;
            float2 v0 = make_float2(c[mt][nt][0]*s, c[mt][nt][1]*s);
            float2 v1 = make_float2(c[mt][nt][2]*s, c[mt][nt][3]*s);
            *(float2*)&C[(size_t)m * SEQ + n]       = v0;
            *(float2*)&C[(size_t)(m + 8) * SEQ + n] = v1;
        }
}

// ---------------------------------------------------------------------------
// K3: softmax in place (unchanged — memory bound, works)
// ---------------------------------------------------------------------------
__global__ __launch_bounds__(256) void k_softmax(float* __restrict__ attn)
{
    float* p = attn + (size_t)blockIdx.x * SEQ;
    const int tid = threadIdx.x;
    float4 v = *(const float4*)&p[tid * 4];
    __shared__ float red[8];

    float mx = fmaxf(fmaxf(v.x, v.y), fmaxf(v.z, v.w));
    #pragma unroll
    for (int o = 16; o > 0; o >>= 1)
        mx = fmaxf(mx, __shfl_xor_sync(0xffffffffu, mx, o));
    if ((tid & 31) == 0) red[tid >> 5] = mx;
    __syncthreads();
    float m = red[0];
    #pragma unroll
    for (int i = 1; i < 8; i++) m = fmaxf(m, red[i]);
    __syncthreads();

    v.x = __expf(v.x - m); v.y = __expf(v.y - m);
    v.z = __expf(v.z - m); v.w = __expf(v.w - m);

    float sum = v.x + v.y + v.z + v.w;
    #pragma unroll
    for (int o = 16; o > 0; o >>= 1)
        sum += __shfl_xor_sync(0xffffffffu, sum, o);
    if ((tid & 31) == 0) red[tid >> 5] = sum;
    __syncthreads();
    float tot = red[0];
    #pragma unroll
    for (int i = 1; i < 8; i++) tot += red[i];

    float inv = 1.0f / tot;
    v.x *= inv; v.y *= inv; v.z *= inv; v.w *= inv;
    *(float4*)&p[tid * 4] = v;
}

// ---------------------------------------------------------------------------
// K4: ctx = P @ V -> split bf16 g_ctx.  Block 128x64, 8 warps (4x2),
// warp tile 32x32, KC=32 (32 chunks of seq).
// ---------------------------------------------------------------------------
__global__ __launch_bounds__(256) void k_ctx(const float* __restrict__ attn)
{
    const int bh = blockIdx.y;
    const int b = bh / NH, h = bh - b * NH;
    const int m0 = blockIdx.x * 128;

    __shared__ bf16 Ah[128*KP], Al[128*KP], Bh[64*KP], Bl[64*KP];

    const int tid = threadIdx.x, lane = tid & 31, w = tid >> 5;
    const int g = lane >> 2, t4 = lane & 3;
    const int wm = w & 3, wn = w >> 2;
    const int lr = tid >> 1, lh = (tid & 1) * 16;
    const int vr = tid >> 2, vh = (tid & 3) * 8;

    const float* A = attn + (size_t)bh * SEQ * SEQ;
    const bf16* vth = g_vt_h + (size_t)bh * HD * SEQ;
    const bf16* vtl = g_vt_l + (size_t)bh * HD * SEQ;

    float c[2][4][4];
    #pragma unroll
    for (int a = 0; a < 2; a++)
        #pragma unroll
        for (int n = 0; n < 4; n++)
            #pragma unroll
            for (int i = 0; i < 4; i++) c[a][n][i] = 0.f;

    for (int k0 = 0; k0 < SEQ; k0 += 32) {
        #pragma unroll
        for (int i = 0; i < 4; i++) {
            float4 v = *(const float4*)&A[(size_t)(m0 + lr) * SEQ + k0 + lh + 4*i];
            bf162 h2a, l2a, h2b, l2b;
            bsplit2(v.x, v.y, h2a, l2a);
            bsplit2(v.z, v.w, h2b, l2b);
            *(bf162*)&Ah[lr*KP + lh + 4*i    ] = h2a;
            *(bf162*)&Ah[lr*KP + lh + 4*i + 2] = h2b;
            *(bf162*)&Al[lr*KP + lh + 4*i    ] = l2a;
            *(bf162*)&Al[lr*KP + lh + 4*i + 2] = l2b;
        }
        *(uint4*)&Bh[vr*KP + vh] = *(const uint4*)&vth[(size_t)vr * SEQ + k0 + vh];
        *(uint4*)&Bl[vr*KP + vh] = *(const uint4*)&vtl[(size_t)vr * SEQ + k0 + vh];
        __syncthreads();
        mma_step<2,4>(Ah, Al, Bh, Bl, wm*32, wn*32, 0,  g, t4, c);
        mma_step<2,4>(Ah, Al, Bh, Bl, wm*32, wn*32, 16, g, t4, c);
        __syncthreads();
    }

    #pragma unroll
    for (int mt = 0; mt < 2; mt++)
        #pragma unroll
        for (int nt = 0; nt < 4; nt++) {
            int n = wn*32 + nt*8 + 2*t4;        // d within head, even
            #pragma unroll
            for (int half = 0; half < 2; half++) {
                int m = m0 + wm*32 + mt*16 + g + 8*half;
                size_t row = (size_t)(b*SEQ + m) * CH + h*HD + n;
                bf162 hv, lv;
                bsplit2(c[mt][nt][2*half], c[mt][nt][2*half+1], hv, lv);
                *(bf162*)&g_ctx_h[row] = hv;
                *(bf162*)&g_ctx_l[row] = lv;
            }
        }
}

// ---------------------------------------------------------------------------
// K5: out = ctx @ w_proj + bias.  Block 128x128, warp tile 64x32, KC=32.
// ---------------------------------------------------------------------------
__global__ __launch_bounds__(256) void k_proj(const float* __restrict__ bias,
                                              float* __restrict__ out)
{
    const int K = CH;
    const int m0 = blockIdx.y * 128, n0 = blockIdx.x * 128;

    __shared__ bf16 Ah[128*KP], Al[128*KP], Bh[128*KP], Bl[128*KP];

    const int tid = threadIdx.x, lane = tid & 31, w = tid >> 5;
    const int g = lane >> 2, t4 = lane & 3;
    const int wm = w & 1, wn = w >> 1;
    const int lr = tid >> 1, lh = (tid & 1) * 16;

    float c[4][4][4];
    #pragma unroll
    for (int a = 0; a < 4; a++)
        #pragma unroll
        for (int b2 = 0; b2 < 4; b2++)
            #pragma unroll
            for (int i = 0; i < 4; i++) c[a][b2][i] = 0.f;

    for (int k0 = 0; k0 < K; k0 += 32) {
        #pragma unroll
        for (int i = 0; i < 2; i++) {
            *(uint4*)&Ah[lr*KP + lh + 8*i] =
                *(const uint4*)&g_ctx_h[(size_t)(m0 + lr) * K + k0 + lh + 8*i];
            *(uint4*)&Al[lr*KP + lh + 8*i] =
                *(const uint4*)&g_ctx_l[(size_t)(m0 + lr) * K + k0 + lh + 8*i];
            *(uint4*)&Bh[lr*KP + lh + 8*i] =
                *(const uint4*)&g_wp_h[(size_t)(n0 + lr) * K + k0 + lh + 8*i];
            *(uint4*)&Bl[lr*KP + lh + 8*i] =
                *(const uint4*)&g_wp_l[(size_t)(n0 + lr) * K + k0 + lh + 8*i];
        }
        __syncthreads();
        mma_step<4,4>(Ah, Al, Bh, Bl, wm*64, wn*32, 0,  g, t4, c);
        mma_step<4,4>(Ah, Al, Bh, Bl, wm*64, wn*32, 16, g, t4, c);
        __syncthreads();
    }

    #pragma unroll
    for (int mt = 0; mt < 4; mt++)
        #pragma unroll
        for (int nt = 0; nt < 4; nt++) {
            int n = n0 + wn*32 + nt*8 + 2*t4;
            float2 bi = *(const float2*)&bias[n];
            int m = m0 + wm*64 + mt*16 + g;
            float2 v0 = make_float2(c[mt][nt][0] + bi.x, c[mt][nt][1] + bi.y);
            float2 v1 = make_float2(c[mt][nt][2] + bi.x, c[mt][nt][3] + bi.y);
            *(float2*)&out[(size_t)m * CH + n]       = v0;
            *(float2*)&out[(size_t)(m + 8) * CH + n] = v1;
        }
}

// ---------------------------------------------------------------------------
extern "C" void kernel_launch(void* const* d_in, const int* in_sizes, int n_in,
                              void* d_out, int out_size)
{
    const float* x      = (const float*)d_in[0];
    const float* w_qkv  = (const float*)d_in[1];
    const float* w_proj = (const float*)d_in[2];
    const float* b_proj = (const float*)d_in[3];

    float* out  = (float*)d_out;
    float* attn = out + (size_t)MROWS * CH;

    bf16 *wq_h, *wq_l, *wp_h, *wp_l;
    cudaGetSymbolAddress((void**)&wq_h, g_wq_h);
    cudaGetSymbolAddress((void**)&wq_l, g_wq_l);
    cudaGetSymbolAddress((void**)&wp_h, g_wp_h);
    cudaGetSymbolAddress((void**)&wp_l, g_wp_l);

    // 0. weight transpose + split (runs every call; ~1% of total)
    k_tw<<<dim3(3*CH/32, CH/32), dim3(32, 8)>>>(w_qkv, wq_h, wq_l, CH, 3*CH);
    k_tw<<<dim3(CH/32,   CH/32), dim3(32, 8)>>>(w_proj, wp_h, wp_l, CH, CH);

    // 1. QKV projection (tensor cores, split bf16)
    k_qkv<<<dim3(3*CH/128, MROWS/128), 256>>>(x);

    // 2. Raw scores -> attn region
    k_scores<<<dim3(SEQ/128, SEQ/128, BHNUM), 256>>>(attn);

    // 3. Softmax in place
    k_softmax<<<dim3(BHNUM * SEQ), 256>>>(attn);

    // 4. ctx = P @ V
    k_ctx<<<dim3(SEQ/128, BHNUM), 256>>>(attn);

    // 5. Output projection + bias
    k_proj<<<dim3(CH/128, MROWS/128), 256>>>(b_proj, out);
}